// round 16
// baseline (speedup 1.0000x reference)
#include <cuda_runtime.h>
#include <cuda_fp16.h>
#include <cuda_bf16.h>

#define N_NODES 50000
#define F_IN    16
#define N_HID   32
#define N_EDGES 1000000
#define EDGE_S  8
#define SROWS   9
#define BN_EPS  1e-3f
#define MSCALE  32.0f
#define MINV    0.03125f
#define NTILES  (N_NODES / 16)     // 3125 exactly
#define NODEB   148                // k_node grid (1 block/SM)
// M layout per node: 384 B (3 aligned 128B lines), bytes PERMUTED in o:
//   byte j of s-row (32B at s*32) holds channel o = pi(j) = (j>>1) + (j&1)*16.
// M stores 32*M; g_agg2 (fp16) carries 32x values (perm cols); k_node folds /32.

__device__ uint4 g_M4[N_NODES * 24];        // 19.2 MB fp8 table
__device__ uint2 g_agg2[N_NODES * 8];       // 3.2 MB fp16 agg, perm cols, 32x
__device__ float g_part[NODEB * N_HID];     // per-block pool partials
__device__ unsigned int g_done;
__device__ uint2  g_Bf[10 * 4 * 32];        // prebuilt B fragments (bf16, x32)
__device__ float4 g_bcp4[8];                // bc permuted, x32

__device__ __forceinline__ void mma_bf16(float d[4], const unsigned int a[4],
                                         unsigned int b0, unsigned int b1) {
    asm volatile(
        "mma.sync.aligned.m16n8k16.row.col.f32.bf16.bf16.f32 "
        "{%0,%1,%2,%3}, {%4,%5,%6,%7}, {%8,%9}, {%0,%1,%2,%3};"
        : "+f"(d[0]), "+f"(d[1]), "+f"(d[2]), "+f"(d[3])
        : "r"(a[0]), "r"(a[1]), "r"(a[2]), "r"(a[3]), "r"(b0), "r"(b1));
}
__device__ __forceinline__ unsigned int cvt2e4(float hi, float lo) {
    unsigned short p;
    asm("cvt.rn.satfinite.e4m3x2.f32 %0, %1, %2;" : "=h"(p) : "f"(hi), "f"(lo));
    return (unsigned int)p;
}
__device__ __forceinline__ unsigned int bf2(float lo, float hi) {
    __nv_bfloat162 h = __floats2bfloat162_rn(lo, hi);
    return *reinterpret_cast<unsigned int*>(&h);
}
__device__ __forceinline__ unsigned int h2u(float lo, float hi) {
    __half2 h = __floats2half2_rn(lo, hi);
    return *reinterpret_cast<unsigned int*>(&h);
}

// ---------------------------------------------------------------------------
// One-time (per replay) fragment-table build + counter reset.
// ---------------------------------------------------------------------------
__global__ void k_binit(const float* __restrict__ Wk, const float* __restrict__ bk,
                        const float* __restrict__ Wr, const float* __restrict__ bc) {
    int idx = blockIdx.x * 256 + threadIdx.x;
    if (idx < 10 * 4 * 32) {
        int l = idx & 31, nt = (idx >> 5) & 3, sg = idx >> 7;
        int t = l & 3, gid = l >> 2;
        int col = nt * 8 + gid;
        const float* Ws = (sg < 8) ? (Wk + sg * F_IN * N_HID)
                                   : ((sg == 8) ? bk : Wr);
        float v0 = Ws[(2*t)   * N_HID + col], v1 = Ws[(2*t+1) * N_HID + col];
        float v2 = Ws[(2*t+8) * N_HID + col], v3 = Ws[(2*t+9) * N_HID + col];
        g_Bf[idx] = make_uint2(bf2(v0 * MSCALE, v1 * MSCALE),
                               bf2(v2 * MSCALE, v3 * MSCALE));
    }
    if (idx < N_HID) {
        int o = (idx >> 1) + ((idx & 1) << 4);        // pi(idx)
        reinterpret_cast<float*>(g_bcp4)[idx] = bc[o] * MSCALE;
    }
    if (idx == 40) g_done = 0;
}

// ---------------------------------------------------------------------------
// Tensor-core precompute: no smem, no syncthreads. Warp = one 16-node tile;
// fragments read from the L1/L2-hot g_Bf table. M table layout unchanged.
// ---------------------------------------------------------------------------
__global__ void __launch_bounds__(256) k_precompute(const float* __restrict__ x) {
    int tid = threadIdx.x;
    int wid = tid >> 5, lane = tid & 31;
    int tile = blockIdx.x * 8 + wid;
    if (tile >= NTILES) return;
    int nb = tile * 16;
    int t = lane & 3, gr = lane >> 2;

    const float2* xr0 = reinterpret_cast<const float2*>(x) + (nb + gr) * 8;
    const float2* xr1 = reinterpret_cast<const float2*>(x) + (nb + gr + 8) * 8;
    unsigned int a[4];
    { float2 v;
      v = xr0[t];     a[0] = bf2(v.x, v.y);
      v = xr1[t];     a[1] = bf2(v.x, v.y);
      v = xr0[t + 4]; a[2] = bf2(v.x, v.y);
      v = xr1[t + 4]; a[3] = bf2(v.x, v.y);
    }

    char* mbase = reinterpret_cast<char*>(g_M4);
#pragma unroll
    for (int sg = 0; sg < 9; sg++) {
        float d[4][4];
#pragma unroll
        for (int nt = 0; nt < 4; nt++) {
            d[nt][0] = d[nt][1] = d[nt][2] = d[nt][3] = 0.f;
            uint2 b = __ldg(&g_Bf[sg * 128 + nt * 32 + lane]);
            mma_bf16(d[nt], a, b.x, b.y);
        }
        unsigned int w00 = (cvt2e4(d[2][1], d[0][1]) << 16) | cvt2e4(d[2][0], d[0][0]);
        unsigned int w01 = (cvt2e4(d[3][1], d[1][1]) << 16) | cvt2e4(d[3][0], d[1][0]);
        unsigned int w10 = (cvt2e4(d[2][3], d[0][3]) << 16) | cvt2e4(d[2][2], d[0][2]);
        unsigned int w11 = (cvt2e4(d[3][3], d[1][3]) << 16) | cvt2e4(d[3][2], d[1][2]);
        long off0 = (long)(nb + gr)     * 384 + sg * 32 + 4 * t;
        long off1 = (long)(nb + gr + 8) * 384 + sg * 32 + 4 * t;
        *reinterpret_cast<unsigned int*>(mbase + off0)      = w00;
        *reinterpret_cast<unsigned int*>(mbase + off0 + 16) = w01;
        *reinterpret_cast<unsigned int*>(mbase + off1)      = w10;
        *reinterpret_cast<unsigned int*>(mbase + off1 + 16) = w11;
    }
    // seed group (Wr): fp16 out + bc, permuted cols, 32x scaled
    {
        float d[4][4];
#pragma unroll
        for (int nt = 0; nt < 4; nt++) {
            d[nt][0] = d[nt][1] = d[nt][2] = d[nt][3] = 0.f;
            uint2 b = __ldg(&g_Bf[9 * 128 + nt * 32 + lane]);
            mma_bf16(d[nt], a, b.x, b.y);
        }
        float4 bl = __ldg(&g_bcp4[t]), bh = __ldg(&g_bcp4[4 + t]);
        g_agg2[(nb + gr) * 8 + t] =
            make_uint2(h2u(d[0][0] + bl.x, d[2][0] + bl.y),
                       h2u(d[0][1] + bl.z, d[2][1] + bl.w));
        g_agg2[(nb + gr) * 8 + 4 + t] =
            make_uint2(h2u(d[1][0] + bh.x, d[3][0] + bh.y),
                       h2u(d[1][1] + bh.z, d[3][1] + bh.w));
        g_agg2[(nb + gr + 8) * 8 + t] =
            make_uint2(h2u(d[0][2] + bl.x, d[2][2] + bl.y),
                       h2u(d[0][3] + bl.z, d[2][3] + bl.w));
        g_agg2[(nb + gr + 8) * 8 + 4 + t] =
            make_uint2(h2u(d[1][2] + bh.x, d[3][2] + bh.y),
                       h2u(d[1][3] + bh.z, d[3][3] + bh.w));
    }
}

// ---------------------------------------------------------------------------
// Per-edge gather + scatter (UNCHANGED). fp16x2 vector RED, at LTS byte cap.
// ---------------------------------------------------------------------------
__device__ __forceinline__ __half2 cvt8(unsigned int v) {
    unsigned int h;
    asm("cvt.rn.f16x2.e4m3x2 %0, %1;" : "=r"(h) : "h"((unsigned short)v));
    return *reinterpret_cast<__half2*>(&h);
}
__device__ __forceinline__ __half2 shx(__half2 v, int m) {
    unsigned int u = *reinterpret_cast<unsigned int*>(&v);
    u = __shfl_xor_sync(0xffffffffu, u, m);
    return *reinterpret_cast<__half2*>(&u);
}

__global__ void __launch_bounds__(256) k_edge(const int* __restrict__ ei,
                                              const float* __restrict__ e) {
    int gtid = blockIdx.x * 256 + threadIdx.x;
    int edge = gtid >> 3;
    if (edge >= N_EDGES) return;
    int g    = threadIdx.x & 7;
    int hidx = g >> 1;
    bool oddh = hidx & 1;
    bool odd2 = (hidx & 2) != 0;

    int2 pe = reinterpret_cast<const int2*>(ei)[edge];
    int src = pe.x, tgt = pe.y;

    __half2 eA = __float2half2_rn(e[edge * EDGE_S + hidx]);
    __half2 eB = __float2half2_rn(e[edge * EDGE_S + 4 + hidx]);

    const uint4* nb = g_M4 + src * 24;
    uint4 q0 = nb[g];
    uint4 q1 = nb[8 + g];

    __half2 r0 = __hmul2(eA, cvt8(q0.x)), r1 = __hmul2(eA, cvt8(q0.x >> 16));
    __half2 r2 = __hmul2(eA, cvt8(q0.y)), r3 = __hmul2(eA, cvt8(q0.y >> 16));
    __half2 r4 = __hmul2(eA, cvt8(q0.z)), r5 = __hmul2(eA, cvt8(q0.z >> 16));
    __half2 r6 = __hmul2(eA, cvt8(q0.w)), r7 = __hmul2(eA, cvt8(q0.w >> 16));
    r0 = __hfma2(eB, cvt8(q1.x), r0); r1 = __hfma2(eB, cvt8(q1.x >> 16), r1);
    r2 = __hfma2(eB, cvt8(q1.y), r2); r3 = __hfma2(eB, cvt8(q1.y >> 16), r3);
    r4 = __hfma2(eB, cvt8(q1.z), r4); r5 = __hfma2(eB, cvt8(q1.z >> 16), r5);
    r6 = __hfma2(eB, cvt8(q1.w), r6); r7 = __hfma2(eB, cvt8(q1.w >> 16), r7);

    __half2 k0 = __hadd2(oddh ? r2 : r0, shx(oddh ? r0 : r2, 2));
    __half2 k1 = __hadd2(oddh ? r3 : r1, shx(oddh ? r1 : r3, 2));
    __half2 k2 = __hadd2(oddh ? r6 : r4, shx(oddh ? r4 : r6, 2));
    __half2 k3 = __hadd2(oddh ? r7 : r5, shx(oddh ? r5 : r7, 2));
    __half2 c0 = __hadd2(odd2 ? k2 : k0, shx(odd2 ? k0 : k2, 4));
    __half2 c1 = __hadd2(odd2 ? k3 : k1, shx(odd2 ? k1 : k3, 4));

    int ochunk = 16 * (g & 1) + 4 * hidx;
    unsigned int m8 = *reinterpret_cast<const unsigned int*>(
        reinterpret_cast<const char*>(nb) + 256 + ochunk);
    c0 = __hadd2(c0, cvt8(m8));
    c1 = __hadd2(c1, cvt8(m8 >> 16));

    char* dst = reinterpret_cast<char*>(g_agg2) + (long)(tgt * N_HID + ochunk) * 2;
    unsigned int C0 = *reinterpret_cast<unsigned int*>(&c0);
    unsigned int C1 = *reinterpret_cast<unsigned int*>(&c1);
    asm volatile("red.global.add.noftz.v2.f16x2 [%0], {%1, %2};"
                 :: "l"(dst), "r"(C0), "r"(C1) : "memory");
}

// ---------------------------------------------------------------------------
// h = BN(relu(agg/32)); pool partial per block (plain STG, no contention);
// last block reduces the 148x32 partial matrix and emits out = pooled@Wd+bd.
// ---------------------------------------------------------------------------
__global__ void __launch_bounds__(256) k_node(const float* __restrict__ gamma,
                                              const float* __restrict__ beta,
                                              const float* __restrict__ mm,
                                              const float* __restrict__ mv,
                                              const float* __restrict__ Wd,
                                              const float* __restrict__ bd,
                                              float* __restrict__ out) {
    __shared__ float4 scl4[8], shf4[8];
    __shared__ float blk[N_HID];
    __shared__ int last;
    int tid = threadIdx.x;
    if (tid < N_HID) {
        blk[tid] = 0.f;
        int o = (tid >> 1) + ((tid & 1) << 4);        // pi(tid)
        float rs = rsqrtf(mv[o] + BN_EPS) * gamma[o];
        reinterpret_cast<float*>(scl4)[tid] = rs * MINV;
        reinterpret_cast<float*>(shf4)[tid] = beta[o] - mm[o] * rs;
    }
    __syncthreads();

    int lane = tid & 31, w = tid >> 5;
    int q = lane & 7, nsub = lane >> 3;
    float4 sc = scl4[q], sh = shf4[q];
    float4 pool = make_float4(0.f, 0.f, 0.f, 0.f);

    for (int base = blockIdx.x * 32; base < N_NODES; base += NODEB * 32) {
        int node = base + w * 4 + nsub;
        if (node < N_NODES) {
            uint2 v = g_agg2[node * 8 + q];
            float2 p01 = __half22float2(*reinterpret_cast<__half2*>(&v.x));
            float2 p23 = __half22float2(*reinterpret_cast<__half2*>(&v.y));
            pool.x += fmaxf(p01.x, 0.f) * sc.x + sh.x;
            pool.y += fmaxf(p01.y, 0.f) * sc.y + sh.y;
            pool.z += fmaxf(p23.x, 0.f) * sc.z + sh.z;
            pool.w += fmaxf(p23.y, 0.f) * sc.w + sh.w;
        }
    }
#pragma unroll
    for (int m = 8; m <= 16; m <<= 1) {
        pool.x += __shfl_xor_sync(0xffffffffu, pool.x, m);
        pool.y += __shfl_xor_sync(0xffffffffu, pool.y, m);
        pool.z += __shfl_xor_sync(0xffffffffu, pool.z, m);
        pool.w += __shfl_xor_sync(0xffffffffu, pool.w, m);
    }
    if (lane < 8) {
        atomicAdd(&blk[4 * lane + 0], pool.x);
        atomicAdd(&blk[4 * lane + 1], pool.y);
        atomicAdd(&blk[4 * lane + 2], pool.z);
        atomicAdd(&blk[4 * lane + 3], pool.w);
    }
    __syncthreads();
    if (tid < N_HID) g_part[blockIdx.x * N_HID + tid] = blk[tid];   // no atomics
    __threadfence();
    if (tid == 0)
        last = (atomicAdd(&g_done, 1u) == NODEB - 1) ? 1 : 0;
    __syncthreads();
    if (last) {
        // warp w sums rows w, w+8, ...; lane = channel; merge via shared atomics
        float acc = 0.f;
        for (int b = w; b < NODEB; b += 8)
            acc += g_part[b * N_HID + lane];
        __syncthreads();          // blk[] free for reuse
        if (tid < N_HID) blk[tid] = 0.f;
        __syncthreads();
        atomicAdd(&blk[lane], acc);
        __syncthreads();
        if (tid < 3) {
            float r = bd[tid];
#pragma unroll
            for (int j = 0; j < N_HID; j++) {
                int oj = (j >> 1) + ((j & 1) << 4);
                r += blk[j] * Wd[oj * 3 + tid];
            }
            out[tid] = r;
        }
    }
}

// ---------------------------------------------------------------------------
extern "C" void kernel_launch(void* const* d_in, const int* in_sizes, int n_in,
                              void* d_out, int out_size) {
    const float* x   = (const float*)d_in[0];
    const int*   ei  = (const int*)  d_in[1];
    const float* e   = (const float*)d_in[2];
    const float* Wk  = (const float*)d_in[3];
    const float* bk  = (const float*)d_in[4];
    const float* Wr  = (const float*)d_in[5];
    const float* bc  = (const float*)d_in[6];
    const float* ga  = (const float*)d_in[7];
    const float* be  = (const float*)d_in[8];
    const float* mm  = (const float*)d_in[9];
    const float* mv  = (const float*)d_in[10];
    const float* Wd  = (const float*)d_in[11];
    const float* bd  = (const float*)d_in[12];
    float* out = (float*)d_out;

    k_binit<<<5, 256>>>(Wk, bk, Wr, bc);
    k_precompute<<<(NTILES + 7) / 8, 256>>>(x);
    k_edge<<<(N_EDGES * 8 + 255) / 256, 256>>>(ei, e);
    k_node<<<NODEB, 256>>>(ga, be, mm, mv, Wd, bd, out);
}

// round 17
// speedup vs baseline: 1.0672x; 1.0672x over previous
#include <cuda_runtime.h>
#include <cuda_fp16.h>
#include <cuda_bf16.h>

#define N_NODES 50000
#define F_IN    16
#define N_HID   32
#define N_EDGES 1000000
#define EDGE_S  8
#define SROWS   9
#define BN_EPS  1e-3f
#define MSCALE  32.0f
#define MINV    0.03125f
#define NTILES  (N_NODES / 16)     // 3125 exactly
#define NODEB   592                // k_node grid
// M layout per node: 384 B (3 aligned 128B lines), bytes PERMUTED in o:
//   byte j of s-row (32B at s*32) holds channel o = pi(j) = (j>>1) + (j&1)*16.
// M stores 32*M; g_agg2 (fp16) carries 32x values (perm cols); k_node folds /32.

__device__ uint4 g_M4[N_NODES * 24];        // 19.2 MB fp8 table
__device__ uint2 g_agg2[N_NODES * 8];       // 3.2 MB fp16 agg, perm cols, 32x
__device__ float g_part[NODEB * N_HID];     // per-block pool partials
__device__ unsigned int g_done;
__device__ uint2  g_Bf[10 * 4 * 32];        // prebuilt B fragments (bf16, x32)
__device__ float4 g_bcp4[8];                // bc permuted, x32

__device__ __forceinline__ void mma_bf16(float d[4], const unsigned int a[4],
                                         unsigned int b0, unsigned int b1) {
    asm volatile(
        "mma.sync.aligned.m16n8k16.row.col.f32.bf16.bf16.f32 "
        "{%0,%1,%2,%3}, {%4,%5,%6,%7}, {%8,%9}, {%0,%1,%2,%3};"
        : "+f"(d[0]), "+f"(d[1]), "+f"(d[2]), "+f"(d[3])
        : "r"(a[0]), "r"(a[1]), "r"(a[2]), "r"(a[3]), "r"(b0), "r"(b1));
}
__device__ __forceinline__ unsigned int cvt2e4(float hi, float lo) {
    unsigned short p;
    asm("cvt.rn.satfinite.e4m3x2.f32 %0, %1, %2;" : "=h"(p) : "f"(hi), "f"(lo));
    return (unsigned int)p;
}
__device__ __forceinline__ unsigned int bf2(float lo, float hi) {
    __nv_bfloat162 h = __floats2bfloat162_rn(lo, hi);
    return *reinterpret_cast<unsigned int*>(&h);
}
__device__ __forceinline__ unsigned int h2u(float lo, float hi) {
    __half2 h = __floats2half2_rn(lo, hi);
    return *reinterpret_cast<unsigned int*>(&h);
}

// ---------------------------------------------------------------------------
// One-time (per replay) fragment-table build + counter reset.
// ---------------------------------------------------------------------------
__global__ void k_binit(const float* __restrict__ Wk, const float* __restrict__ bk,
                        const float* __restrict__ Wr, const float* __restrict__ bc) {
    int idx = blockIdx.x * 256 + threadIdx.x;
    if (idx < 10 * 4 * 32) {
        int l = idx & 31, nt = (idx >> 5) & 3, sg = idx >> 7;
        int t = l & 3, gid = l >> 2;
        int col = nt * 8 + gid;
        const float* Ws = (sg < 8) ? (Wk + sg * F_IN * N_HID)
                                   : ((sg == 8) ? bk : Wr);
        float v0 = Ws[(2*t)   * N_HID + col], v1 = Ws[(2*t+1) * N_HID + col];
        float v2 = Ws[(2*t+8) * N_HID + col], v3 = Ws[(2*t+9) * N_HID + col];
        g_Bf[idx] = make_uint2(bf2(v0 * MSCALE, v1 * MSCALE),
                               bf2(v2 * MSCALE, v3 * MSCALE));
    }
    if (idx < N_HID) {
        int o = (idx >> 1) + ((idx & 1) << 4);        // pi(idx)
        reinterpret_cast<float*>(g_bcp4)[idx] = bc[o] * MSCALE;
    }
    if (idx == 40) g_done = 0;
}

// ---------------------------------------------------------------------------
// Tensor-core precompute (UNCHANGED): no smem, no syncthreads.
// ---------------------------------------------------------------------------
__global__ void __launch_bounds__(256) k_precompute(const float* __restrict__ x) {
    int tid = threadIdx.x;
    int wid = tid >> 5, lane = tid & 31;
    int tile = blockIdx.x * 8 + wid;
    if (tile >= NTILES) return;
    int nb = tile * 16;
    int t = lane & 3, gr = lane >> 2;

    const float2* xr0 = reinterpret_cast<const float2*>(x) + (nb + gr) * 8;
    const float2* xr1 = reinterpret_cast<const float2*>(x) + (nb + gr + 8) * 8;
    unsigned int a[4];
    { float2 v;
      v = xr0[t];     a[0] = bf2(v.x, v.y);
      v = xr1[t];     a[1] = bf2(v.x, v.y);
      v = xr0[t + 4]; a[2] = bf2(v.x, v.y);
      v = xr1[t + 4]; a[3] = bf2(v.x, v.y);
    }

    char* mbase = reinterpret_cast<char*>(g_M4);
#pragma unroll
    for (int sg = 0; sg < 9; sg++) {
        float d[4][4];
#pragma unroll
        for (int nt = 0; nt < 4; nt++) {
            d[nt][0] = d[nt][1] = d[nt][2] = d[nt][3] = 0.f;
            uint2 b = __ldg(&g_Bf[sg * 128 + nt * 32 + lane]);
            mma_bf16(d[nt], a, b.x, b.y);
        }
        unsigned int w00 = (cvt2e4(d[2][1], d[0][1]) << 16) | cvt2e4(d[2][0], d[0][0]);
        unsigned int w01 = (cvt2e4(d[3][1], d[1][1]) << 16) | cvt2e4(d[3][0], d[1][0]);
        unsigned int w10 = (cvt2e4(d[2][3], d[0][3]) << 16) | cvt2e4(d[2][2], d[0][2]);
        unsigned int w11 = (cvt2e4(d[3][3], d[1][3]) << 16) | cvt2e4(d[3][2], d[1][2]);
        long off0 = (long)(nb + gr)     * 384 + sg * 32 + 4 * t;
        long off1 = (long)(nb + gr + 8) * 384 + sg * 32 + 4 * t;
        *reinterpret_cast<unsigned int*>(mbase + off0)      = w00;
        *reinterpret_cast<unsigned int*>(mbase + off0 + 16) = w01;
        *reinterpret_cast<unsigned int*>(mbase + off1)      = w10;
        *reinterpret_cast<unsigned int*>(mbase + off1 + 16) = w11;
    }
    {
        float d[4][4];
#pragma unroll
        for (int nt = 0; nt < 4; nt++) {
            d[nt][0] = d[nt][1] = d[nt][2] = d[nt][3] = 0.f;
            uint2 b = __ldg(&g_Bf[9 * 128 + nt * 32 + lane]);
            mma_bf16(d[nt], a, b.x, b.y);
        }
        float4 bl = __ldg(&g_bcp4[t]), bh = __ldg(&g_bcp4[4 + t]);
        g_agg2[(nb + gr) * 8 + t] =
            make_uint2(h2u(d[0][0] + bl.x, d[2][0] + bl.y),
                       h2u(d[0][1] + bl.z, d[2][1] + bl.w));
        g_agg2[(nb + gr) * 8 + 4 + t] =
            make_uint2(h2u(d[1][0] + bh.x, d[3][0] + bh.y),
                       h2u(d[1][1] + bh.z, d[3][1] + bh.w));
        g_agg2[(nb + gr + 8) * 8 + t] =
            make_uint2(h2u(d[0][2] + bl.x, d[2][2] + bl.y),
                       h2u(d[0][3] + bl.z, d[2][3] + bl.w));
        g_agg2[(nb + gr + 8) * 8 + 4 + t] =
            make_uint2(h2u(d[1][2] + bh.x, d[3][2] + bh.y),
                       h2u(d[1][3] + bh.z, d[3][3] + bh.w));
    }
}

// ---------------------------------------------------------------------------
// Per-edge gather + scatter (UNCHANGED). fp16x2 vector RED, at LTS byte cap.
// ---------------------------------------------------------------------------
__device__ __forceinline__ __half2 cvt8(unsigned int v) {
    unsigned int h;
    asm("cvt.rn.f16x2.e4m3x2 %0, %1;" : "=r"(h) : "h"((unsigned short)v));
    return *reinterpret_cast<__half2*>(&h);
}
__device__ __forceinline__ __half2 shx(__half2 v, int m) {
    unsigned int u = *reinterpret_cast<unsigned int*>(&v);
    u = __shfl_xor_sync(0xffffffffu, u, m);
    return *reinterpret_cast<__half2*>(&u);
}

__global__ void __launch_bounds__(256) k_edge(const int* __restrict__ ei,
                                              const float* __restrict__ e) {
    int gtid = blockIdx.x * 256 + threadIdx.x;
    int edge = gtid >> 3;
    if (edge >= N_EDGES) return;
    int g    = threadIdx.x & 7;
    int hidx = g >> 1;
    bool oddh = hidx & 1;
    bool odd2 = (hidx & 2) != 0;

    int2 pe = reinterpret_cast<const int2*>(ei)[edge];
    int src = pe.x, tgt = pe.y;

    __half2 eA = __float2half2_rn(e[edge * EDGE_S + hidx]);
    __half2 eB = __float2half2_rn(e[edge * EDGE_S + 4 + hidx]);

    const uint4* nb = g_M4 + src * 24;
    uint4 q0 = nb[g];
    uint4 q1 = nb[8 + g];

    __half2 r0 = __hmul2(eA, cvt8(q0.x)), r1 = __hmul2(eA, cvt8(q0.x >> 16));
    __half2 r2 = __hmul2(eA, cvt8(q0.y)), r3 = __hmul2(eA, cvt8(q0.y >> 16));
    __half2 r4 = __hmul2(eA, cvt8(q0.z)), r5 = __hmul2(eA, cvt8(q0.z >> 16));
    __half2 r6 = __hmul2(eA, cvt8(q0.w)), r7 = __hmul2(eA, cvt8(q0.w >> 16));
    r0 = __hfma2(eB, cvt8(q1.x), r0); r1 = __hfma2(eB, cvt8(q1.x >> 16), r1);
    r2 = __hfma2(eB, cvt8(q1.y), r2); r3 = __hfma2(eB, cvt8(q1.y >> 16), r3);
    r4 = __hfma2(eB, cvt8(q1.z), r4); r5 = __hfma2(eB, cvt8(q1.z >> 16), r5);
    r6 = __hfma2(eB, cvt8(q1.w), r6); r7 = __hfma2(eB, cvt8(q1.w >> 16), r7);

    __half2 k0 = __hadd2(oddh ? r2 : r0, shx(oddh ? r0 : r2, 2));
    __half2 k1 = __hadd2(oddh ? r3 : r1, shx(oddh ? r1 : r3, 2));
    __half2 k2 = __hadd2(oddh ? r6 : r4, shx(oddh ? r4 : r6, 2));
    __half2 k3 = __hadd2(oddh ? r7 : r5, shx(oddh ? r5 : r7, 2));
    __half2 c0 = __hadd2(odd2 ? k2 : k0, shx(odd2 ? k0 : k2, 4));
    __half2 c1 = __hadd2(odd2 ? k3 : k1, shx(odd2 ? k1 : k3, 4));

    int ochunk = 16 * (g & 1) + 4 * hidx;
    unsigned int m8 = *reinterpret_cast<const unsigned int*>(
        reinterpret_cast<const char*>(nb) + 256 + ochunk);
    c0 = __hadd2(c0, cvt8(m8));
    c1 = __hadd2(c1, cvt8(m8 >> 16));

    char* dst = reinterpret_cast<char*>(g_agg2) + (long)(tgt * N_HID + ochunk) * 2;
    unsigned int C0 = *reinterpret_cast<unsigned int*>(&c0);
    unsigned int C1 = *reinterpret_cast<unsigned int*>(&c1);
    asm volatile("red.global.add.noftz.v2.f16x2 [%0], {%1, %2};"
                 :: "l"(dst), "r"(C0), "r"(C1) : "memory");
}

// ---------------------------------------------------------------------------
// h = BN(relu(agg/32)); pool. Grid 592 for latency coverage; uint4 loads
// (8 ch/thread, 64 nodes/block-iter); partial-store epilogue (no global
// same-address atomics); counter-elected last block reduces 592x32 + 1x3 GEMM.
// ---------------------------------------------------------------------------
__global__ void __launch_bounds__(256) k_node(const float* __restrict__ gamma,
                                              const float* __restrict__ beta,
                                              const float* __restrict__ mm,
                                              const float* __restrict__ mv,
                                              const float* __restrict__ Wd,
                                              const float* __restrict__ bd,
                                              float* __restrict__ out) {
    __shared__ float4 scl4[8], shf4[8];
    __shared__ float blk[N_HID];
    __shared__ int last;
    int tid = threadIdx.x;
    if (tid < N_HID) {
        blk[tid] = 0.f;
        int o = (tid >> 1) + ((tid & 1) << 4);        // pi(tid)
        float rs = rsqrtf(mv[o] + BN_EPS) * gamma[o];
        reinterpret_cast<float*>(scl4)[tid] = rs * MINV;
        reinterpret_cast<float*>(shf4)[tid] = beta[o] - mm[o] * rs;
    }
    __syncthreads();

    int lane = tid & 31, w = tid >> 5;
    int q2 = lane & 3, nsub = lane >> 2;            // q2: uint4 idx (8 ch)
    float4 scA = scl4[2 * q2],     shA = shf4[2 * q2];
    float4 scB = scl4[2 * q2 + 1], shB = shf4[2 * q2 + 1];
    float4 pA = make_float4(0.f, 0.f, 0.f, 0.f);
    float4 pB = make_float4(0.f, 0.f, 0.f, 0.f);

    const uint4* ag4 = reinterpret_cast<const uint4*>(g_agg2);
    for (int base = blockIdx.x * 64; base < N_NODES; base += NODEB * 64) {
        int node = base + w * 8 + nsub;
        if (node < N_NODES) {
            uint4 v = ag4[node * 4 + q2];
            float2 a0 = __half22float2(*reinterpret_cast<__half2*>(&v.x));
            float2 a1 = __half22float2(*reinterpret_cast<__half2*>(&v.y));
            float2 a2 = __half22float2(*reinterpret_cast<__half2*>(&v.z));
            float2 a3 = __half22float2(*reinterpret_cast<__half2*>(&v.w));
            pA.x += fmaxf(a0.x, 0.f) * scA.x + shA.x;
            pA.y += fmaxf(a0.y, 0.f) * scA.y + shA.y;
            pA.z += fmaxf(a1.x, 0.f) * scA.z + shA.z;
            pA.w += fmaxf(a1.y, 0.f) * scA.w + shA.w;
            pB.x += fmaxf(a2.x, 0.f) * scB.x + shB.x;
            pB.y += fmaxf(a2.y, 0.f) * scB.y + shB.y;
            pB.z += fmaxf(a3.x, 0.f) * scB.z + shB.z;
            pB.w += fmaxf(a3.y, 0.f) * scB.w + shB.w;
        }
    }
#pragma unroll
    for (int m = 4; m <= 16; m <<= 1) {
        pA.x += __shfl_xor_sync(0xffffffffu, pA.x, m);
        pA.y += __shfl_xor_sync(0xffffffffu, pA.y, m);
        pA.z += __shfl_xor_sync(0xffffffffu, pA.z, m);
        pA.w += __shfl_xor_sync(0xffffffffu, pA.w, m);
        pB.x += __shfl_xor_sync(0xffffffffu, pB.x, m);
        pB.y += __shfl_xor_sync(0xffffffffu, pB.y, m);
        pB.z += __shfl_xor_sync(0xffffffffu, pB.z, m);
        pB.w += __shfl_xor_sync(0xffffffffu, pB.w, m);
    }
    if (lane < 4) {
        int c = 8 * lane;
        atomicAdd(&blk[c + 0], pA.x); atomicAdd(&blk[c + 1], pA.y);
        atomicAdd(&blk[c + 2], pA.z); atomicAdd(&blk[c + 3], pA.w);
        atomicAdd(&blk[c + 4], pB.x); atomicAdd(&blk[c + 5], pB.y);
        atomicAdd(&blk[c + 6], pB.z); atomicAdd(&blk[c + 7], pB.w);
    }
    __syncthreads();
    if (tid < N_HID) g_part[blockIdx.x * N_HID + tid] = blk[tid];   // no atomics
    __threadfence();
    if (tid == 0)
        last = (atomicAdd(&g_done, 1u) == NODEB - 1) ? 1 : 0;
    __syncthreads();
    if (last) {
        // warp w sums rows w, w+8, ... (74 rows); lane = channel
        float a0 = 0.f, a1 = 0.f;
        for (int b = w; b + 8 < NODEB; b += 16) {
            a0 += g_part[b * N_HID + lane];
            a1 += g_part[(b + 8) * N_HID + lane];
        }
        if ((NODEB - 1 - w) % 16 < 8)    // odd remainder row for this warp
            a0 += g_part[(w + ((NODEB - 8 - w) / 16) * 16 + 8) * N_HID + lane];
        float acc = a0 + a1;
        __syncthreads();
        if (tid < N_HID) blk[tid] = 0.f;
        __syncthreads();
        atomicAdd(&blk[lane], acc);
        __syncthreads();
        if (tid < 3) {
            float r = bd[tid];
#pragma unroll
            for (int j = 0; j < N_HID; j++) {
                int oj = (j >> 1) + ((j & 1) << 4);
                r += blk[j] * Wd[oj * 3 + tid];
            }
            out[tid] = r;
        }
    }
}

// ---------------------------------------------------------------------------
extern "C" void kernel_launch(void* const* d_in, const int* in_sizes, int n_in,
                              void* d_out, int out_size) {
    const float* x   = (const float*)d_in[0];
    const int*   ei  = (const int*)  d_in[1];
    const float* e   = (const float*)d_in[2];
    const float* Wk  = (const float*)d_in[3];
    const float* bk  = (const float*)d_in[4];
    const float* Wr  = (const float*)d_in[5];
    const float* bc  = (const float*)d_in[6];
    const float* ga  = (const float*)d_in[7];
    const float* be  = (const float*)d_in[8];
    const float* mm  = (const float*)d_in[9];
    const float* mv  = (const float*)d_in[10];
    const float* Wd  = (const float*)d_in[11];
    const float* bd  = (const float*)d_in[12];
    float* out = (float*)d_out;

    k_binit<<<5, 256>>>(Wk, bk, Wr, bc);
    k_precompute<<<(NTILES + 7) / 8, 256>>>(x);
    k_edge<<<(N_EDGES * 8 + 255) / 256, 256>>>(ei, e);
    k_node<<<NODEB, 256>>>(ga, be, mm, mv, Wd, bd, out);
}